// round 1
// baseline (speedup 1.0000x reference)
#include <cuda_runtime.h>
#include <math.h>
#include <stdint.h>

// ---------------------------------------------------------------------------
// TransformerXL layer, fp32 SIMT baseline (round 0).
// B=4, Q=1024, D=1024, N=16 heads, DH=64, DFF=4096.
// ---------------------------------------------------------------------------

#define QLEN   1024
#define DMODEL 1024
#define NHEAD  16
#define DHEAD  64
#define DFF    4096
#define BATCHN 4
#define ROWS   (BATCHN * QLEN)     // 4096
#define D3     (3 * DMODEL)        // 3072
#define BN_TOT (BATCHN * NHEAD)    // 64

// Scratch (static __device__ globals: allocation-free per harness rules)
__device__ float g_heads[(size_t)ROWS * D3];               // QKV projections, 48 MB
__device__ float g_rk[(size_t)QLEN * DMODEL];              // r @ r_w^T, 4 MB
__device__ float g_S[(size_t)BN_TOT * QLEN * QLEN];        // AC scores, then probs (in place), 256 MB
__device__ float g_P[(size_t)BN_TOT * QLEN * QLEN];        // BD (pre-shift) scores, 256 MB
__device__ float g_av[(size_t)ROWS * DMODEL];              // attention output, 16 MB
__device__ float g_tmp[(size_t)ROWS * DMODEL];             // o-proj, then ff2, 16 MB
__device__ float g_out1[(size_t)ROWS * DMODEL];            // post-LN1, 16 MB
__device__ float g_ff1[(size_t)ROWS * DFF];                // relu(ff1), 64 MB

// ---------------------------------------------------------------------------
// Big dense NT GEMM: C[M,N] = A[M,K] * B[N,K]^T (+bias) (+relu)
// A row-major lda=K, B row-major ldb=K, C row-major ldc=N.
// 128x128 tile, BK=8, 256 threads, 8x8 per thread.
// All dims are multiples of (128,128,8) in this problem -> no bounds checks.
// ---------------------------------------------------------------------------
template <bool BIAS, bool RELU>
__global__ __launch_bounds__(256) void gemm_nt128(
    const float* __restrict__ A, const float* __restrict__ B,
    const float* __restrict__ bias, float* __restrict__ C,
    int M, int N, int K)
{
    __shared__ float As[8][128];
    __shared__ float Bs[8][128];

    const int tid  = threadIdx.x;
    const int lrow = tid >> 1;           // 0..127 (load row)
    const int lcol = (tid & 1) << 2;     // 0 or 4
    const int tx   = tid & 15;           // 0..15
    const int ty   = tid >> 4;           // 0..15

    const float* Ab = A + (size_t)blockIdx.y * 128 * K;
    const float* Bb = B + (size_t)blockIdx.x * 128 * K;

    float acc[8][8];
#pragma unroll
    for (int i = 0; i < 8; i++)
#pragma unroll
        for (int j = 0; j < 8; j++) acc[i][j] = 0.0f;

    for (int kt = 0; kt < K; kt += 8) {
        float4 a4 = *(const float4*)(Ab + (size_t)lrow * K + kt + lcol);
        float4 b4 = *(const float4*)(Bb + (size_t)lrow * K + kt + lcol);
        As[lcol + 0][lrow] = a4.x; As[lcol + 1][lrow] = a4.y;
        As[lcol + 2][lrow] = a4.z; As[lcol + 3][lrow] = a4.w;
        Bs[lcol + 0][lrow] = b4.x; Bs[lcol + 1][lrow] = b4.y;
        Bs[lcol + 2][lrow] = b4.z; Bs[lcol + 3][lrow] = b4.w;
        __syncthreads();

#pragma unroll
        for (int k = 0; k < 8; k++) {
            float4 a0 = *(const float4*)&As[k][ty * 8];
            float4 a1 = *(const float4*)&As[k][ty * 8 + 4];
            float4 b0 = *(const float4*)&Bs[k][tx * 8];
            float4 b1 = *(const float4*)&Bs[k][tx * 8 + 4];
            float ar[8] = {a0.x, a0.y, a0.z, a0.w, a1.x, a1.y, a1.z, a1.w};
            float br[8] = {b0.x, b0.y, b0.z, b0.w, b1.x, b1.y, b1.z, b1.w};
#pragma unroll
            for (int i = 0; i < 8; i++)
#pragma unroll
                for (int j = 0; j < 8; j++)
                    acc[i][j] = fmaf(ar[i], br[j], acc[i][j]);
        }
        __syncthreads();
    }

    const int crow = blockIdx.y * 128 + ty * 8;
    const int ccol = blockIdx.x * 128 + tx * 8;
    float bv[8];
#pragma unroll
    for (int j = 0; j < 8; j++) bv[j] = BIAS ? bias[ccol + j] : 0.0f;

#pragma unroll
    for (int i = 0; i < 8; i++) {
        float* Crow = C + (size_t)(crow + i) * N + ccol;
        float v[8];
#pragma unroll
        for (int j = 0; j < 8; j++) {
            float x = acc[i][j] + bv[j];
            if (RELU) x = fmaxf(x, 0.0f);
            v[j] = x;
        }
        *(float4*)(Crow)     = make_float4(v[0], v[1], v[2], v[3]);
        *(float4*)(Crow + 4) = make_float4(v[4], v[5], v[6], v[7]);
    }
}

// ---------------------------------------------------------------------------
// Batched attention score GEMM (NT, K=64), 64x64 tile, BK=16, 256 threads,
// 4x4 per thread. Bias (r_w_bias / r_r_bias) is added to A on load.
// MODE 0: AC  -> C[i,j]  = (q_i + rwb_n) . k_j       (skip j-tile above diag)
// MODE 1: P   -> C[i,jr] = (q_i + rrb_n) . rk_jr     (skip unused anti-region)
// ---------------------------------------------------------------------------
template <int MODE>
__global__ __launch_bounds__(256) void attn_score(
    const float* __restrict__ heads, const float* __restrict__ rk,
    const float* __restrict__ bias_all, float* __restrict__ out)
{
    const int batch = blockIdx.z;
    const int b = batch >> 4;
    const int n = batch & 15;
    const int i0 = blockIdx.y << 6;
    const int j0 = blockIdx.x << 6;

    if (MODE == 0) { if (j0 > i0 + 63) return; }                 // causal: need j <= i only
    else           { if (i0 + j0 + 126 < QLEN - 1) return; }     // need jr >= Q-1-i only

    const float* Ab = heads + (size_t)b * QLEN * D3 + (size_t)i0 * D3 + n * DHEAD;
    const float* Bb;
    int ldb;
    if (MODE == 0) { Bb = heads + (size_t)b * QLEN * D3 + (size_t)j0 * D3 + DMODEL + n * DHEAD; ldb = D3; }
    else           { Bb = rk + (size_t)j0 * DMODEL + n * DHEAD; ldb = DMODEL; }
    const float* bias = bias_all + n * DHEAD;
    float* Cb = out + (size_t)batch * QLEN * QLEN;

    __shared__ float As[16][64];
    __shared__ float Bs[16][64];
    __shared__ float bsm[64];

    const int tid  = threadIdx.x;
    if (tid < 64) bsm[tid] = bias[tid];
    __syncthreads();

    const int lrow = tid >> 2;           // 0..63
    const int lcol = (tid & 3) << 2;     // 0,4,8,12
    const int tx   = tid & 15;
    const int ty   = tid >> 4;

    float acc[4][4] = {};

#pragma unroll
    for (int kt = 0; kt < DHEAD; kt += 16) {
        float4 a4 = *(const float4*)(Ab + (size_t)lrow * D3 + kt + lcol);
        float4 b4 = *(const float4*)(Bb + (size_t)lrow * ldb + kt + lcol);
        As[lcol + 0][lrow] = a4.x + bsm[kt + lcol + 0];
        As[lcol + 1][lrow] = a4.y + bsm[kt + lcol + 1];
        As[lcol + 2][lrow] = a4.z + bsm[kt + lcol + 2];
        As[lcol + 3][lrow] = a4.w + bsm[kt + lcol + 3];
        Bs[lcol + 0][lrow] = b4.x; Bs[lcol + 1][lrow] = b4.y;
        Bs[lcol + 2][lrow] = b4.z; Bs[lcol + 3][lrow] = b4.w;
        __syncthreads();

#pragma unroll
        for (int k = 0; k < 16; k++) {
            float ar[4], br[4];
#pragma unroll
            for (int i = 0; i < 4; i++) ar[i] = As[k][ty * 4 + i];
#pragma unroll
            for (int j = 0; j < 4; j++) br[j] = Bs[k][tx * 4 + j];
#pragma unroll
            for (int i = 0; i < 4; i++)
#pragma unroll
                for (int j = 0; j < 4; j++)
                    acc[i][j] = fmaf(ar[i], br[j], acc[i][j]);
        }
        __syncthreads();
    }

#pragma unroll
    for (int i = 0; i < 4; i++) {
        *(float4*)(Cb + (size_t)(i0 + ty * 4 + i) * QLEN + j0 + tx * 4) =
            make_float4(acc[i][0], acc[i][1], acc[i][2], acc[i][3]);
    }
}

// ---------------------------------------------------------------------------
// Softmax over klen with rel-shift fusion. One block per (row i, batch b*n).
// score[j] = (AC[i,j] + P[i, Q-1-i+j]) / 8 for j<=i, else -inf.
// Writes probabilities in place over the AC buffer (zeros for j>i).
// ---------------------------------------------------------------------------
__global__ __launch_bounds__(256) void softmax_k(
    float* __restrict__ S, const float* __restrict__ P)
{
    const int i = blockIdx.x;
    const int batch = blockIdx.y;
    float* rowS = S + ((size_t)batch * QLEN + i) * QLEN;
    const float* rowP = P + ((size_t)batch * QLEN + i) * QLEN;
    const int tid = threadIdx.x;

    __shared__ float red[8];

    float s[4];
    float m = -INFINITY;
#pragma unroll
    for (int c = 0; c < 4; c++) {
        int j = tid + (c << 8);
        if (j <= i) s[c] = (rowS[j] + rowP[QLEN - 1 - i + j]) * 0.125f;
        else        s[c] = -INFINITY;
        m = fmaxf(m, s[c]);
    }
#pragma unroll
    for (int o = 16; o; o >>= 1) m = fmaxf(m, __shfl_xor_sync(0xffffffffu, m, o));
    if ((tid & 31) == 0) red[tid >> 5] = m;
    __syncthreads();
    float mf = red[0];
#pragma unroll
    for (int w = 1; w < 8; w++) mf = fmaxf(mf, red[w]);
    __syncthreads();

    float sum = 0.0f;
#pragma unroll
    for (int c = 0; c < 4; c++) { s[c] = __expf(s[c] - mf); sum += s[c]; }
#pragma unroll
    for (int o = 16; o; o >>= 1) sum += __shfl_xor_sync(0xffffffffu, sum, o);
    if ((tid & 31) == 0) red[tid >> 5] = sum;
    __syncthreads();
    float sf = red[0];
#pragma unroll
    for (int w = 1; w < 8; w++) sf += red[w];
    float inv = 1.0f / sf;

#pragma unroll
    for (int c = 0; c < 4; c++) {
        int j = tid + (c << 8);
        rowS[j] = s[c] * inv;   // exact 0 for j > i
    }
}

// ---------------------------------------------------------------------------
// Batched AV GEMM (NN): C[i,d] = sum_j prob[i,j] * v[j,d] per (b,n).
// 64x64 tile, BK=16. K-loop truncated at i0+64 (probs are 0 beyond the diag).
// ---------------------------------------------------------------------------
__global__ __launch_bounds__(256) void attn_av(
    const float* __restrict__ prob, const float* __restrict__ heads,
    float* __restrict__ av)
{
    const int batch = blockIdx.z;
    const int b = batch >> 4;
    const int n = batch & 15;
    const int i0 = blockIdx.y << 6;

    const float* Ab = prob + (size_t)batch * QLEN * QLEN + (size_t)i0 * QLEN;
    const float* Bb = heads + (size_t)b * QLEN * D3 + 2 * DMODEL + n * DHEAD;
    float* Cb = av + (size_t)b * QLEN * DMODEL + (size_t)i0 * DMODEL + n * DHEAD;

    __shared__ float As[16][64];
    __shared__ float Bs[16][64];

    const int tid  = threadIdx.x;
    const int arow = tid >> 2;           // 0..63
    const int acol = (tid & 3) << 2;     // 0,4,8,12
    const int brow = tid >> 4;           // 0..15
    const int bcol = (tid & 15) << 2;    // 0..60
    const int tx   = tid & 15;
    const int ty   = tid >> 4;

    float acc[4][4] = {};
    const int kmax = i0 + 64;

    for (int kt = 0; kt < kmax; kt += 16) {
        float4 a4 = *(const float4*)(Ab + (size_t)arow * QLEN + kt + acol);
        float4 b4 = *(const float4*)(Bb + (size_t)(kt + brow) * D3 + bcol);
        As[acol + 0][arow] = a4.x; As[acol + 1][arow] = a4.y;
        As[acol + 2][arow] = a4.z; As[acol + 3][arow] = a4.w;
        *(float4*)&Bs[brow][bcol] = b4;
        __syncthreads();

#pragma unroll
        for (int k = 0; k < 16; k++) {
            float ar[4], br[4];
#pragma unroll
            for (int i = 0; i < 4; i++) ar[i] = As[k][ty * 4 + i];
#pragma unroll
            for (int j = 0; j < 4; j++) br[j] = Bs[k][tx * 4 + j];
#pragma unroll
            for (int i = 0; i < 4; i++)
#pragma unroll
                for (int j = 0; j < 4; j++)
                    acc[i][j] = fmaf(ar[i], br[j], acc[i][j]);
        }
        __syncthreads();
    }

#pragma unroll
    for (int i = 0; i < 4; i++) {
        *(float4*)(Cb + (size_t)(ty * 4 + i) * DMODEL + tx * 4) =
            make_float4(acc[i][0], acc[i][1], acc[i][2], acc[i][3]);
    }
}

// ---------------------------------------------------------------------------
// out = LayerNorm(a + b) * gamma + beta. One block (256 thr) per 1024-el row.
// ---------------------------------------------------------------------------
__global__ __launch_bounds__(256) void add_ln(
    const float* __restrict__ a, const float* __restrict__ bb,
    const float* __restrict__ gamma, const float* __restrict__ beta,
    float* __restrict__ out)
{
    const int row = blockIdx.x;
    const size_t base = (size_t)row * DMODEL;
    const int tid = threadIdx.x;
    __shared__ float red[8];

    float x[4];
    float sum = 0.0f;
#pragma unroll
    for (int c = 0; c < 4; c++) {
        int j = tid + (c << 8);
        x[c] = a[base + j] + bb[base + j];
        sum += x[c];
    }
#pragma unroll
    for (int o = 16; o; o >>= 1) sum += __shfl_xor_sync(0xffffffffu, sum, o);
    if ((tid & 31) == 0) red[tid >> 5] = sum;
    __syncthreads();
    float tot = red[0];
#pragma unroll
    for (int w = 1; w < 8; w++) tot += red[w];
    __syncthreads();
    const float mean = tot * (1.0f / DMODEL);

    float vs = 0.0f;
#pragma unroll
    for (int c = 0; c < 4; c++) { float d = x[c] - mean; vs += d * d; }
#pragma unroll
    for (int o = 16; o; o >>= 1) vs += __shfl_xor_sync(0xffffffffu, vs, o);
    if ((tid & 31) == 0) red[tid >> 5] = vs;
    __syncthreads();
    float vtot = red[0];
#pragma unroll
    for (int w = 1; w < 8; w++) vtot += red[w];
    const float rstd = rsqrtf(vtot * (1.0f / DMODEL) + 1e-5f);

#pragma unroll
    for (int c = 0; c < 4; c++) {
        int j = tid + (c << 8);
        out[base + j] = (x[c] - mean) * rstd * gamma[j] + beta[j];
    }
}

// ---------------------------------------------------------------------------
// Launcher
// ---------------------------------------------------------------------------
extern "C" void kernel_launch(void* const* d_in, const int* in_sizes, int n_in,
                              void* d_out, int out_size)
{
    (void)in_sizes; (void)n_in; (void)out_size;

    const float* w        = (const float*)d_in[0];
    const float* r        = (const float*)d_in[1];
    // d_in[2] = attention_mask: unused (causal structure is hard-coded)
    const float* qkv_w    = (const float*)d_in[3];
    const float* r_w      = (const float*)d_in[4];
    const float* o_w      = (const float*)d_in[5];
    const float* r_w_bias = (const float*)d_in[6];
    const float* r_r_bias = (const float*)d_in[7];
    const float* ln1_g    = (const float*)d_in[8];
    const float* ln1_b    = (const float*)d_in[9];
    const float* ff_w1    = (const float*)d_in[10];
    const float* ff_b1    = (const float*)d_in[11];
    const float* ff_w2    = (const float*)d_in[12];
    const float* ff_b2    = (const float*)d_in[13];
    const float* ln2_g    = (const float*)d_in[14];
    const float* ln2_b    = (const float*)d_in[15];
    float* out = (float*)d_out;

    float *heads, *rk, *S, *P, *av, *tmp, *out1, *ff1;
    cudaGetSymbolAddress((void**)&heads, g_heads);
    cudaGetSymbolAddress((void**)&rk,    g_rk);
    cudaGetSymbolAddress((void**)&S,     g_S);
    cudaGetSymbolAddress((void**)&P,     g_P);
    cudaGetSymbolAddress((void**)&av,    g_av);
    cudaGetSymbolAddress((void**)&tmp,   g_tmp);
    cudaGetSymbolAddress((void**)&out1,  g_out1);
    cudaGetSymbolAddress((void**)&ff1,   g_ff1);

    const dim3 blk(256);

    // 1) QKV projection: heads[4096,3072] = w @ qkv_w^T
    gemm_nt128<false, false><<<dim3(D3 / 128, ROWS / 128), blk>>>(
        w, qkv_w, nullptr, heads, ROWS, D3, DMODEL);

    // 2) rk[1024,1024] = r @ r_w^T
    gemm_nt128<false, false><<<dim3(DMODEL / 128, QLEN / 128), blk>>>(
        r, r_w, nullptr, rk, QLEN, DMODEL, DMODEL);

    // 3) AC[b,n,i,j] = (q+rwb).k   (causal tiles only)
    attn_score<0><<<dim3(16, 16, BN_TOT), blk>>>(heads, rk, r_w_bias, S);

    // 4) P[b,n,i,jr] = (q+rrb).rk  (needed anti-region only)
    attn_score<1><<<dim3(16, 16, BN_TOT), blk>>>(heads, rk, r_r_bias, P);

    // 5) softmax with rel-shift + causal mask, in place over S
    softmax_k<<<dim3(QLEN, BN_TOT), blk>>>(S, P);

    // 6) av = prob @ v
    attn_av<<<dim3(1, 16, BN_TOT), blk>>>(S, heads, av);

    // 7) o-projection: tmp = av @ o_w^T
    gemm_nt128<false, false><<<dim3(DMODEL / 128, ROWS / 128), blk>>>(
        av, o_w, nullptr, tmp, ROWS, DMODEL, DMODEL);

    // 8) out1 = LN(w + tmp)
    add_ln<<<ROWS, blk>>>(w, tmp, ln1_g, ln1_b, out1);

    // 9) ff1 = relu(out1 @ ff_w1^T + b1)
    gemm_nt128<true, true><<<dim3(DFF / 128, ROWS / 128), blk>>>(
        out1, ff_w1, ff_b1, ff1, ROWS, DFF, DMODEL);

    // 10) tmp = ff1 @ ff_w2^T + b2
    gemm_nt128<true, false><<<dim3(DMODEL / 128, ROWS / 128), blk>>>(
        ff1, ff_w2, ff_b2, tmp, ROWS, DMODEL, DFF);

    // 11) out = LN(out1 + tmp)
    add_ln<<<ROWS, blk>>>(out1, tmp, ln2_g, ln2_b, out);
}

// round 3
// speedup vs baseline: 2.2242x; 2.2242x over previous
#include <cuda_runtime.h>
#include <cuda_bf16.h>
#include <math.h>
#include <stdint.h>

// ---------------------------------------------------------------------------
// TransformerXL layer, round 3: dense GEMMs on mma.sync bf16 (split-bf16,
// fp32 accumulate), attention fp32 SIMT.
// B=4, Q=1024, D=1024, N=16 heads, DH=64, DFF=4096.
// ---------------------------------------------------------------------------

#define QLEN   1024
#define DMODEL 1024
#define NHEAD  16
#define DHEAD  64
#define DFF    4096
#define BATCHN 4
#define ROWS   (BATCHN * QLEN)     // 4096
#define D3     (3 * DMODEL)        // 3072
#define BN_TOT (BATCHN * NHEAD)    // 64

typedef __nv_bfloat16 bf16;

// ---------------- scratch (device globals; allocation-free) ----------------
__device__ float g_heads[(size_t)ROWS * D3];
__device__ float g_rk[(size_t)QLEN * DMODEL];
__device__ float g_S[(size_t)BN_TOT * QLEN * QLEN];
__device__ float g_P[(size_t)BN_TOT * QLEN * QLEN];
__device__ float g_av[(size_t)ROWS * DMODEL];
__device__ float g_tmp[(size_t)ROWS * DMODEL];
__device__ float g_out1[(size_t)ROWS * DMODEL];

__device__ bf16 g_wh[(size_t)ROWS * DMODEL],   g_wl[(size_t)ROWS * DMODEL];
__device__ bf16 g_rh[(size_t)QLEN * DMODEL],   g_rl[(size_t)QLEN * DMODEL];
__device__ bf16 g_qwh[(size_t)D3 * DMODEL],    g_qwl[(size_t)D3 * DMODEL];
__device__ bf16 g_rwh[(size_t)DMODEL * DMODEL],g_rwl[(size_t)DMODEL * DMODEL];
__device__ bf16 g_owh[(size_t)DMODEL * DMODEL],g_owl[(size_t)DMODEL * DMODEL];
__device__ bf16 g_f1h[(size_t)DFF * DMODEL],   g_f1l[(size_t)DFF * DMODEL];
__device__ bf16 g_f2h[(size_t)DMODEL * DFF],   g_f2l[(size_t)DMODEL * DFF];
__device__ bf16 g_avh[(size_t)ROWS * DMODEL],  g_avl[(size_t)ROWS * DMODEL];
__device__ bf16 g_o1h[(size_t)ROWS * DMODEL],  g_o1l[(size_t)ROWS * DMODEL];
__device__ bf16 g_ff1h[(size_t)ROWS * DFF],    g_ff1l[(size_t)ROWS * DFF];

// ---------------------------------------------------------------------------
// PTX helpers (sm_80-level only: cp.async, ldmatrix, mma.sync)
// ---------------------------------------------------------------------------
__device__ __forceinline__ uint32_t cvta_smem(const void* p) {
    uint32_t a;
    asm("{ .reg .u64 t; cvta.to.shared.u64 t, %1; cvt.u32.u64 %0, t; }"
        : "=r"(a) : "l"(p));
    return a;
}
#define SWZ(o) ((o) ^ (((o) >> 3) & 0x70))

__device__ __forceinline__ void cp16(uint32_t dst, const void* src) {
    asm volatile("cp.async.cg.shared.global [%0], [%1], 16;" :: "r"(dst), "l"(src));
}
__device__ __forceinline__ void cp_commit() {
    asm volatile("cp.async.commit_group;" ::: "memory");
}
template <int N> __device__ __forceinline__ void cp_wait() {
    asm volatile("cp.async.wait_group %0;" :: "n"(N) : "memory");
}
__device__ __forceinline__ void ldsm_x4(uint32_t& r0, uint32_t& r1,
                                        uint32_t& r2, uint32_t& r3, uint32_t a) {
    asm volatile("ldmatrix.sync.aligned.m8n8.x4.shared.b16 {%0,%1,%2,%3}, [%4];"
                 : "=r"(r0), "=r"(r1), "=r"(r2), "=r"(r3) : "r"(a));
}
__device__ __forceinline__ void ldsm_x2(uint32_t& r0, uint32_t& r1, uint32_t a) {
    asm volatile("ldmatrix.sync.aligned.m8n8.x2.shared.b16 {%0,%1}, [%2];"
                 : "=r"(r0), "=r"(r1) : "r"(a));
}
__device__ __forceinline__ void mma_bf16(float* c, uint32_t a0, uint32_t a1,
                                         uint32_t a2, uint32_t a3,
                                         uint32_t b0, uint32_t b1) {
    asm volatile(
        "mma.sync.aligned.m16n8k16.row.col.f32.bf16.bf16.f32 "
        "{%0,%1,%2,%3}, {%4,%5,%6,%7}, {%8,%9}, {%0,%1,%2,%3};"
        : "+f"(c[0]), "+f"(c[1]), "+f"(c[2]), "+f"(c[3])
        : "r"(a0), "r"(a1), "r"(a2), "r"(a3), "r"(b0), "r"(b1));
}

// ---------------------------------------------------------------------------
// mma.sync GEMM: C[M,N] = A[M,K] @ B[N,K]^T with split-bf16 inputs.
// 3 passes (Ah*Bh, Ah*Bl, Al*Bh) into the same fp32 accumulators.
// Block 128x128, K chunk 64 bf16 (128B rows, SW128), 3-stage cp.async ring,
// 8 warps (2m x 4n), warp tile 64x32, mma m16n8k16.
// ---------------------------------------------------------------------------
#define TM 128
#define TN 128
#define KC 64
#define STAGES 3
#define GT 256

#define ASTAGE  (TM * 128)                        // 16384 bytes
#define BSTAGE  (TN * 128)                        // 16384 bytes
#define STG     (ASTAGE + BSTAGE)                 // 32768
#define SM_A    1024
#define GEMM_SMEM (SM_A + STAGES * STG)           // 99328

template <bool BIAS, bool RELU, bool OUTF, bool OUTS>
__global__ __launch_bounds__(GT) void gemm_tc(
    const bf16* __restrict__ Ah, const bf16* __restrict__ Al,
    const bf16* __restrict__ Bh, const bf16* __restrict__ Bl,
    const float* __restrict__ bias, float* __restrict__ C,
    bf16* __restrict__ Ch, bf16* __restrict__ Cl,
    int N, int K)
{
    extern __shared__ char smem[];
    const uint32_t sbase = cvta_smem(smem);
    const int tid  = threadIdx.x;
    const int lane = tid & 31;
    const int warp = tid >> 5;
    const int wm   = warp >> 2;          // 0..1
    const int wn   = warp & 3;           // 0..3
    const int i0   = blockIdx.y * TM;
    const int j0   = blockIdx.x * TN;

    if (BIAS) { if (tid < TN) ((float*)smem)[tid] = bias[j0 + tid]; }

    const int ncpp = K / KC;
    const int NC   = 3 * ncpp;

    auto load_chunk = [&](int c) {
        const int p = c / ncpp, kc = c - p * ncpp;
        const bf16* Asrc = (p == 2) ? Al : Ah;
        const bf16* Bsrc = (p == 1) ? Bl : Bh;
        const int st = c % STAGES;
        const uint32_t abase = sbase + SM_A + st * STG;
        const uint32_t bbase = abase + ASTAGE;
        const char* ag = (const char*)(Asrc + (size_t)i0 * K + kc * KC);
        const char* bg = (const char*)(Bsrc + (size_t)j0 * K + kc * KC);
#pragma unroll
        for (int it = 0; it < 4; it++) {
            int s = tid + it * GT;       // 0..1023
            int row = s >> 3, sc = s & 7;
            cp16(abase + SWZ(row * 128 + sc * 16),
                 ag + (size_t)row * (K * 2) + sc * 16);
        }
#pragma unroll
        for (int it = 0; it < 4; it++) {
            int s = tid + it * GT;
            int row = s >> 3, sc = s & 7;
            cp16(bbase + SWZ(row * 128 + sc * 16),
                 bg + (size_t)row * (K * 2) + sc * 16);
        }
    };

    float acc[4][4][4];
#pragma unroll
    for (int mt = 0; mt < 4; mt++)
#pragma unroll
        for (int nt = 0; nt < 4; nt++)
#pragma unroll
            for (int e = 0; e < 4; e++) acc[mt][nt][e] = 0.0f;

    // prologue
#pragma unroll
    for (int c = 0; c < STAGES - 1; c++) { load_chunk(c); cp_commit(); }

    // precomputed intra-tile fragment offsets
    const int a_row = wm * 64 + (lane & 15);
    const int a_ko  = (lane >> 4) * 16;
    const int b_row = wn * 32 + (lane & 7);
    const int b_ko  = ((lane >> 3) & 1) * 16;

    for (int c = 0; c < NC; c++) {
        const int cl = c + STAGES - 1;
        if (cl < NC) load_chunk(cl);
        cp_commit();
        cp_wait<STAGES - 1>();
        __syncthreads();

        const int st = c % STAGES;
        const uint32_t abase = sbase + SM_A + st * STG;
        const uint32_t bbase = abase + ASTAGE;

#pragma unroll
        for (int ks = 0; ks < 4; ks++) {
            uint32_t bfr[4][2];
#pragma unroll
            for (int nt = 0; nt < 4; nt++) {
                int off = (b_row + nt * 8) * 128 + ks * 32 + b_ko;
                ldsm_x2(bfr[nt][0], bfr[nt][1], bbase + SWZ(off));
            }
#pragma unroll
            for (int mt = 0; mt < 4; mt++) {
                int off = (a_row + mt * 16) * 128 + ks * 32 + a_ko;
                uint32_t a0, a1, a2, a3;
                ldsm_x4(a0, a1, a2, a3, abase + SWZ(off));
#pragma unroll
                for (int nt = 0; nt < 4; nt++)
                    mma_bf16(acc[mt][nt], a0, a1, a2, a3, bfr[nt][0], bfr[nt][1]);
            }
        }
        __syncthreads();
    }

    // epilogue
    const int er = lane >> 2;            // 0..7
    const int ec = (lane & 3) * 2;       // 0,2,4,6
#pragma unroll
    for (int mt = 0; mt < 4; mt++) {
#pragma unroll
        for (int nt = 0; nt < 4; nt++) {
            const int col = wn * 32 + nt * 8 + ec;
            float b0 = 0.0f, b1 = 0.0f;
            if (BIAS) { b0 = ((float*)smem)[col]; b1 = ((float*)smem)[col + 1]; }
#pragma unroll
            for (int h = 0; h < 2; h++) {
                const int row = i0 + wm * 64 + mt * 16 + er + h * 8;
                float v0 = acc[mt][nt][2 * h]     + b0;
                float v1 = acc[mt][nt][2 * h + 1] + b1;
                if (RELU) { v0 = fmaxf(v0, 0.0f); v1 = fmaxf(v1, 0.0f); }
                if (OUTF) {
                    *(float2*)(C + (size_t)row * N + j0 + col) = make_float2(v0, v1);
                }
                if (OUTS) {
                    bf16 h0 = __float2bfloat16_rn(v0);
                    bf16 h1 = __float2bfloat16_rn(v1);
                    bf16 l0 = __float2bfloat16_rn(v0 - __bfloat162float(h0));
                    bf16 l1 = __float2bfloat16_rn(v1 - __bfloat162float(h1));
                    __nv_bfloat162 hp; hp.x = h0; hp.y = h1;
                    __nv_bfloat162 lp; lp.x = l0; lp.y = l1;
                    *(__nv_bfloat162*)(Ch + (size_t)row * N + j0 + col) = hp;
                    *(__nv_bfloat162*)(Cl + (size_t)row * N + j0 + col) = lp;
                }
            }
        }
    }
}

// ---------------------------------------------------------------------------
// fp32 -> bf16 hi/lo split
// ---------------------------------------------------------------------------
__global__ __launch_bounds__(256) void split_bf16(
    const float4* __restrict__ x, uint2* __restrict__ h, uint2* __restrict__ l,
    int n4)
{
    int i = blockIdx.x * 256 + threadIdx.x;
    if (i >= n4) return;
    float4 v = x[i];
    bf16 h0 = __float2bfloat16_rn(v.x), h1 = __float2bfloat16_rn(v.y);
    bf16 h2 = __float2bfloat16_rn(v.z), h3 = __float2bfloat16_rn(v.w);
    bf16 l0 = __float2bfloat16_rn(v.x - __bfloat162float(h0));
    bf16 l1 = __float2bfloat16_rn(v.y - __bfloat162float(h1));
    bf16 l2 = __float2bfloat16_rn(v.z - __bfloat162float(h2));
    bf16 l3 = __float2bfloat16_rn(v.w - __bfloat162float(h3));
    __nv_bfloat162 p01, p23, q01, q23;
    p01.x = h0; p01.y = h1; p23.x = h2; p23.y = h3;
    q01.x = l0; q01.y = l1; q23.x = l2; q23.y = l3;
    uint2 hh, ll;
    hh.x = *(uint32_t*)&p01; hh.y = *(uint32_t*)&p23;
    ll.x = *(uint32_t*)&q01; ll.y = *(uint32_t*)&q23;
    h[i] = hh; l[i] = ll;
}

// ---------------------------------------------------------------------------
// Attention (fp32 SIMT, same as round 1)
// ---------------------------------------------------------------------------
template <int MODE>
__global__ __launch_bounds__(256) void attn_score(
    const float* __restrict__ heads, const float* __restrict__ rk,
    const float* __restrict__ bias_all, float* __restrict__ out)
{
    const int batch = blockIdx.z;
    const int b = batch >> 4;
    const int n = batch & 15;
    const int i0 = blockIdx.y << 6;
    const int j0 = blockIdx.x << 6;

    if (MODE == 0) { if (j0 > i0 + 63) return; }
    else           { if (i0 + j0 + 126 < QLEN - 1) return; }

    const float* Ab = heads + (size_t)b * QLEN * D3 + (size_t)i0 * D3 + n * DHEAD;
    const float* Bb;
    int ldb;
    if (MODE == 0) { Bb = heads + (size_t)b * QLEN * D3 + (size_t)j0 * D3 + DMODEL + n * DHEAD; ldb = D3; }
    else           { Bb = rk + (size_t)j0 * DMODEL + n * DHEAD; ldb = DMODEL; }
    const float* bias = bias_all + n * DHEAD;
    float* Cb = out + (size_t)batch * QLEN * QLEN;

    __shared__ float As[16][64];
    __shared__ float Bs[16][64];
    __shared__ float bsm[64];

    const int tid = threadIdx.x;
    if (tid < 64) bsm[tid] = bias[tid];
    __syncthreads();

    const int lrow = tid >> 2;
    const int lcol = (tid & 3) << 2;
    const int tx = tid & 15;
    const int ty = tid >> 4;

    float acc[4][4] = {};

#pragma unroll
    for (int kt = 0; kt < DHEAD; kt += 16) {
        float4 a4 = *(const float4*)(Ab + (size_t)lrow * D3 + kt + lcol);
        float4 b4 = *(const float4*)(Bb + (size_t)lrow * ldb + kt + lcol);
        As[lcol + 0][lrow] = a4.x + bsm[kt + lcol + 0];
        As[lcol + 1][lrow] = a4.y + bsm[kt + lcol + 1];
        As[lcol + 2][lrow] = a4.z + bsm[kt + lcol + 2];
        As[lcol + 3][lrow] = a4.w + bsm[kt + lcol + 3];
        Bs[lcol + 0][lrow] = b4.x; Bs[lcol + 1][lrow] = b4.y;
        Bs[lcol + 2][lrow] = b4.z; Bs[lcol + 3][lrow] = b4.w;
        __syncthreads();

#pragma unroll
        for (int k = 0; k < 16; k++) {
            float ar[4], br[4];
#pragma unroll
            for (int i = 0; i < 4; i++) ar[i] = As[k][ty * 4 + i];
#pragma unroll
            for (int j = 0; j < 4; j++) br[j] = Bs[k][tx * 4 + j];
#pragma unroll
            for (int i = 0; i < 4; i++)
#pragma unroll
                for (int j = 0; j < 4; j++)
                    acc[i][j] = fmaf(ar[i], br[j], acc[i][j]);
        }
        __syncthreads();
    }

#pragma unroll
    for (int i = 0; i < 4; i++) {
        *(float4*)(Cb + (size_t)(i0 + ty * 4 + i) * QLEN + j0 + tx * 4) =
            make_float4(acc[i][0], acc[i][1], acc[i][2], acc[i][3]);
    }
}

__global__ __launch_bounds__(256) void softmax_k(
    float* __restrict__ S, const float* __restrict__ P)
{
    const int i = blockIdx.x;
    const int batch = blockIdx.y;
    float* rowS = S + ((size_t)batch * QLEN + i) * QLEN;
    const float* rowP = P + ((size_t)batch * QLEN + i) * QLEN;
    const int tid = threadIdx.x;

    __shared__ float red[8];

    float s[4];
    float m = -INFINITY;
#pragma unroll
    for (int c = 0; c < 4; c++) {
        int j = tid + (c << 8);
        if (j <= i) s[c] = (rowS[j] + rowP[QLEN - 1 - i + j]) * 0.125f;
        else        s[c] = -INFINITY;
        m = fmaxf(m, s[c]);
    }
#pragma unroll
    for (int o = 16; o; o >>= 1) m = fmaxf(m, __shfl_xor_sync(0xffffffffu, m, o));
    if ((tid & 31) == 0) red[tid >> 5] = m;
    __syncthreads();
    float mf = red[0];
#pragma unroll
    for (int w = 1; w < 8; w++) mf = fmaxf(mf, red[w]);
    __syncthreads();

    float sum = 0.0f;
#pragma unroll
    for (int c = 0; c < 4; c++) { s[c] = __expf(s[c] - mf); sum += s[c]; }
#pragma unroll
    for (int o = 16; o; o >>= 1) sum += __shfl_xor_sync(0xffffffffu, sum, o);
    if ((tid & 31) == 0) red[tid >> 5] = sum;
    __syncthreads();
    float sf = red[0];
#pragma unroll
    for (int w = 1; w < 8; w++) sf += red[w];
    float inv = 1.0f / sf;

#pragma unroll
    for (int c = 0; c < 4; c++) {
        int j = tid + (c << 8);
        rowS[j] = s[c] * inv;
    }
}

__global__ __launch_bounds__(256) void attn_av(
    const float* __restrict__ prob, const float* __restrict__ heads,
    float* __restrict__ av)
{
    const int batch = blockIdx.z;
    const int b = batch >> 4;
    const int n = batch & 15;
    const int i0 = blockIdx.y << 6;

    const float* Ab = prob + (size_t)batch * QLEN * QLEN + (size_t)i0 * QLEN;
    const float* Bb = heads + (size_t)b * QLEN * D3 + 2 * DMODEL + n * DHEAD;
    float* Cb = av + (size_t)b * QLEN * DMODEL + (size_t)i0 * DMODEL + n * DHEAD;

    __shared__ float As[16][64];
    __shared__ float Bs[16][64];

    const int tid = threadIdx.x;
    const int arow = tid >> 2;
    const int acol = (tid & 3) << 2;
    const int brow = tid >> 4;
    const int bcol = (tid & 15) << 2;
    const int tx = tid & 15;
    const int ty = tid >> 4;

    float acc[4][4] = {};
    const int kmax = i0 + 64;

    for (int kt = 0; kt < kmax; kt += 16) {
        float4 a4 = *(const float4*)(Ab + (size_t)arow * QLEN + kt + acol);
        float4 b4 = *(const float4*)(Bb + (size_t)(kt + brow) * D3 + bcol);
        As[acol + 0][arow] = a4.x; As[acol + 1][arow] = a4.y;
        As[acol + 2][arow] = a4.z; As[acol + 3][arow] = a4.w;
        *(float4*)&Bs[brow][bcol] = b4;
        __syncthreads();

#pragma unroll
        for (int k = 0; k < 16; k++) {
            float ar[4], br[4];
#pragma unroll
            for (int i = 0; i < 4; i++) ar[i] = As[k][ty * 4 + i];
#pragma unroll
            for (int j = 0; j < 4; j++) br[j] = Bs[k][tx * 4 + j];
#pragma unroll
            for (int i = 0; i < 4; i++)
#pragma unroll
                for (int j = 0; j < 4; j++)
                    acc[i][j] = fmaf(ar[i], br[j], acc[i][j]);
        }
        __syncthreads();
    }

#pragma unroll
    for (int i = 0; i < 4; i++) {
        *(float4*)(Cb + (size_t)(ty * 4 + i) * DMODEL + tx * 4) =
            make_float4(acc[i][0], acc[i][1], acc[i][2], acc[i][3]);
    }
}

// ---------------------------------------------------------------------------
// out = LayerNorm(a + b) (+ optional bf16 hi/lo emission)
// ---------------------------------------------------------------------------
template <bool SPLIT>
__global__ __launch_bounds__(256) void add_ln(
    const float* __restrict__ a, const float* __restrict__ bb,
    const float* __restrict__ gamma, const float* __restrict__ beta,
    float* __restrict__ out, bf16* __restrict__ oh, bf16* __restrict__ ol)
{
    const int row = blockIdx.x;
    const size_t base = (size_t)row * DMODEL;
    const int tid = threadIdx.x;
    __shared__ float red[8];

    float x[4];
    float sum = 0.0f;
#pragma unroll
    for (int c = 0; c < 4; c++) {
        int j = tid + (c << 8);
        x[c] = a[base + j] + bb[base + j];
        sum += x[c];
    }
#pragma unroll
    for (int o = 16; o; o >>= 1) sum += __shfl_xor_sync(0xffffffffu, sum, o);
    if ((tid & 31) == 0) red[tid >> 5] = sum;
    __syncthreads();
    float tot = red[0];
#pragma unroll
    for (int w = 1; w < 8; w++) tot += red[w];
    __syncthreads();
    const float mean = tot * (1.0f / DMODEL);

    float vs = 0.0f;
#pragma unroll
    for (int c = 0; c < 4; c++) { float d = x[c] - mean; vs += d * d; }
#pragma unroll
    for (int o = 16; o; o >>= 1) vs += __shfl_xor_sync(0xffffffffu, vs, o);
    if ((tid & 31) == 0) red[tid >> 5] = vs;
    __syncthreads();
    float vtot = red[0];
#pragma unroll
    for (int w = 1; w < 8; w++) vtot += red[w];
    const float rstd = rsqrtf(vtot * (1.0f / DMODEL) + 1e-5f);

#pragma unroll
    for (int c = 0; c < 4; c++) {
        int j = tid + (c << 8);
        float y = (x[c] - mean) * rstd * gamma[j] + beta[j];
        out[base + j] = y;
        if (SPLIT) {
            bf16 h = __float2bfloat16_rn(y);
            bf16 l = __float2bfloat16_rn(y - __bfloat162float(h));
            oh[base + j] = h;
            ol[base + j] = l;
        }
    }
}

// ---------------------------------------------------------------------------
// Launcher
// ---------------------------------------------------------------------------
extern "C" void kernel_launch(void* const* d_in, const int* in_sizes, int n_in,
                              void* d_out, int out_size)
{
    (void)in_sizes; (void)n_in; (void)out_size;

    const float* w        = (const float*)d_in[0];
    const float* r        = (const float*)d_in[1];
    const float* qkv_w    = (const float*)d_in[3];
    const float* r_w      = (const float*)d_in[4];
    const float* o_w      = (const float*)d_in[5];
    const float* r_w_bias = (const float*)d_in[6];
    const float* r_r_bias = (const float*)d_in[7];
    const float* ln1_g    = (const float*)d_in[8];
    const float* ln1_b    = (const float*)d_in[9];
    const float* ff_w1    = (const float*)d_in[10];
    const float* ff_b1    = (const float*)d_in[11];
    const float* ff_w2    = (const float*)d_in[12];
    const float* ff_b2    = (const float*)d_in[13];
    const float* ln2_g    = (const float*)d_in[14];
    const float* ln2_b    = (const float*)d_in[15];
    float* out = (float*)d_out;

    float *heads, *rk, *S, *P, *av, *tmp, *out1;
    cudaGetSymbolAddress((void**)&heads, g_heads);
    cudaGetSymbolAddress((void**)&rk,    g_rk);
    cudaGetSymbolAddress((void**)&S,     g_S);
    cudaGetSymbolAddress((void**)&P,     g_P);
    cudaGetSymbolAddress((void**)&av,    g_av);
    cudaGetSymbolAddress((void**)&tmp,   g_tmp);
    cudaGetSymbolAddress((void**)&out1,  g_out1);

    bf16 *wh, *wl, *rh, *rl, *qwh, *qwl, *rwh, *rwl, *owh, *owl;
    bf16 *f1h, *f1l, *f2h, *f2l, *avh, *avl, *o1h, *o1l, *ff1h, *ff1l;
    cudaGetSymbolAddress((void**)&wh,  g_wh);  cudaGetSymbolAddress((void**)&wl,  g_wl);
    cudaGetSymbolAddress((void**)&rh,  g_rh);  cudaGetSymbolAddress((void**)&rl,  g_rl);
    cudaGetSymbolAddress((void**)&qwh, g_qwh); cudaGetSymbolAddress((void**)&qwl, g_qwl);
    cudaGetSymbolAddress((void**)&rwh, g_rwh); cudaGetSymbolAddress((void**)&rwl, g_rwl);
    cudaGetSymbolAddress((void**)&owh, g_owh); cudaGetSymbolAddress((void**)&owl, g_owl);
    cudaGetSymbolAddress((void**)&f1h, g_f1h); cudaGetSymbolAddress((void**)&f1l, g_f1l);
    cudaGetSymbolAddress((void**)&f2h, g_f2h); cudaGetSymbolAddress((void**)&f2l, g_f2l);
    cudaGetSymbolAddress((void**)&avh, g_avh); cudaGetSymbolAddress((void**)&avl, g_avl);
    cudaGetSymbolAddress((void**)&o1h, g_o1h); cudaGetSymbolAddress((void**)&o1l, g_o1l);
    cudaGetSymbolAddress((void**)&ff1h, g_ff1h); cudaGetSymbolAddress((void**)&ff1l, g_ff1l);

    cudaFuncSetAttribute(gemm_tc<false, false, true, false>,
                         cudaFuncAttributeMaxDynamicSharedMemorySize, GEMM_SMEM);
    cudaFuncSetAttribute(gemm_tc<true, true, false, true>,
                         cudaFuncAttributeMaxDynamicSharedMemorySize, GEMM_SMEM);
    cudaFuncSetAttribute(gemm_tc<true, false, true, false>,
                         cudaFuncAttributeMaxDynamicSharedMemorySize, GEMM_SMEM);

    const dim3 blk(256);
    auto split = [&](const float* x, bf16* h, bf16* l, size_t n) {
        int n4 = (int)(n / 4);
        split_bf16<<<(n4 + 255) / 256, blk>>>((const float4*)x, (uint2*)h, (uint2*)l, n4);
    };

    // 0) splits of external inputs / weights
    split(w,     wh,  wl,  (size_t)ROWS * DMODEL);
    split(r,     rh,  rl,  (size_t)QLEN * DMODEL);
    split(qkv_w, qwh, qwl, (size_t)D3 * DMODEL);
    split(r_w,   rwh, rwl, (size_t)DMODEL * DMODEL);
    split(o_w,   owh, owl, (size_t)DMODEL * DMODEL);
    split(ff_w1, f1h, f1l, (size_t)DFF * DMODEL);
    split(ff_w2, f2h, f2l, (size_t)DMODEL * DFF);

    // 1) heads = w @ qkv_w^T  [4096 x 3072]
    gemm_tc<false, false, true, false><<<dim3(D3 / TN, ROWS / TM), blk, GEMM_SMEM>>>(
        wh, wl, qwh, qwl, nullptr, heads, nullptr, nullptr, D3, DMODEL);

    // 2) rk = r @ r_w^T  [1024 x 1024]
    gemm_tc<false, false, true, false><<<dim3(DMODEL / TN, QLEN / TM), blk, GEMM_SMEM>>>(
        rh, rl, rwh, rwl, nullptr, rk, nullptr, nullptr, DMODEL, DMODEL);

    // 3-6) attention (fp32 SIMT)
    attn_score<0><<<dim3(16, 16, BN_TOT), blk>>>(heads, rk, r_w_bias, S);
    attn_score<1><<<dim3(16, 16, BN_TOT), blk>>>(heads, rk, r_r_bias, P);
    softmax_k<<<dim3(QLEN, BN_TOT), blk>>>(S, P);
    attn_av<<<dim3(1, 16, BN_TOT), blk>>>(S, heads, av);

    // 7) split av, o-projection
    split(av, avh, avl, (size_t)ROWS * DMODEL);
    gemm_tc<false, false, true, false><<<dim3(DMODEL / TN, ROWS / TM), blk, GEMM_SMEM>>>(
        avh, avl, owh, owl, nullptr, tmp, nullptr, nullptr, DMODEL, DMODEL);

    // 8) out1 = LN(w + tmp), with bf16 split emission
    add_ln<true><<<ROWS, blk>>>(w, tmp, ln1_g, ln1_b, out1, o1h, o1l);

    // 9) ff1 = relu(out1 @ ff_w1^T + b1)  -> bf16 hi/lo only
    gemm_tc<true, true, false, true><<<dim3(DFF / TN, ROWS / TM), blk, GEMM_SMEM>>>(
        o1h, o1l, f1h, f1l, ff_b1, nullptr, ff1h, ff1l, DFF, DMODEL);

    // 10) tmp = ff1 @ ff_w2^T + b2
    gemm_tc<true, false, true, false><<<dim3(DMODEL / TN, ROWS / TM), blk, GEMM_SMEM>>>(
        ff1h, ff1l, f2h, f2l, ff_b2, tmp, nullptr, nullptr, DMODEL, DFF);

    // 11) out = LN(out1 + tmp)
    add_ln<false><<<ROWS, blk>>>(out1, tmp, ln2_g, ln2_b, out, nullptr, nullptr);
}